// round 13
// baseline (speedup 1.0000x reference)
#include <cuda_runtime.h>
#include <cuda_bf16.h>

#define BN 256
#define TN 2048
#define HN 64
#define GN 192   /* 3*H */
#define MBS 8    /* batches per scan block */

// ---------------------------------------------------------------------------
// Scratch (no allocation allowed -> __device__ globals)
// NOTE: scan prefetch deliberately over/under-runs one row past its direction
// slab; layout [2][...] keeps those accesses inside this object.
// ---------------------------------------------------------------------------
__device__ float g_gx[2][(size_t)BN * TN * GN];        // per-direction input gates
__device__ float g_out0[(size_t)BN * TN * 2 * HN];     // layer-0 output [B*T, 128]
__device__ float g_emb[BN * 2 * HN];                   // layer-1 final states [B, 128]

__device__ __forceinline__ float sigf(float x) {
    return __fdividef(1.f, 1.f + __expf(-x));
}
__device__ __forceinline__ float tanhfast(float x) {
    x = fminf(fmaxf(x, -15.f), 15.f);
    float e = __expf(-2.f * x);
    return __fdividef(1.f - e, 1.f + e);
}

// Packed fp32x2 helpers (Blackwell dual-rate fp32 path)
#define FFMA2(acc, a, b) \
    asm("fma.rn.f32x2 %0, %1, %2, %0;" : "+l"(acc) : "l"(a), "l"(b))

__device__ __forceinline__ unsigned long long packdup(float v) {
    unsigned long long r;
    asm("mov.b64 %0, {%1, %1};" : "=l"(r) : "f"(v));
    return r;
}
__device__ __forceinline__ float2 unpack2(unsigned long long p) {
    float2 f;
    asm("mov.b64 {%0, %1}, %2;" : "=f"(f.x), "=f"(f.y) : "l"(p));
    return f;
}

// ---------------------------------------------------------------------------
// Input-gate GEMM: gx[row, g] = bih[g] + sum_i in[row, i] * Wih[g, i]
// 64 rows/block, 192 threads (one gate each), K chunked by 32 via smem.
// ---------------------------------------------------------------------------
template <int IN>
__global__ __launch_bounds__(192) void gx_kernel(
    const float* __restrict__ xin, int use_out0,
    const float* __restrict__ Wf, const float* __restrict__ bf,
    const float* __restrict__ Wb, const float* __restrict__ bb)
{
    const int dir = blockIdx.y;
    const float* __restrict__ W    = dir ? Wb : Wf;
    const float* __restrict__ bias = dir ? bb : bf;
    const float* __restrict__ in   = use_out0 ? g_out0 : xin;
    float* __restrict__ gx = g_gx[dir];
    const int tid = threadIdx.x;
    const long rowbase = (long)blockIdx.x * 64;

    __shared__ float Wsh[32 * 193];   // [i][g]
    __shared__ float xsh[32 * 68];    // [i][r], 16B-aligned rows

    unsigned long long acc2[32];      // 32 packed pairs = 64 row accumulators
#pragma unroll
    for (int rv = 0; rv < 32; rv++) acc2[rv] = 0ull;

#pragma unroll
    for (int kc = 0; kc < IN; kc += 32) {
        const int kw = (IN - kc < 32) ? (IN - kc) : 32;
        for (int idx = tid; idx < kw * 192; idx += 192) {
            int g = idx / kw, i = idx - g * kw;
            Wsh[i * 193 + g] = W[(long)g * IN + kc + i];
        }
        for (int idx = tid; idx < kw * 64; idx += 192) {
            int r = idx / kw, i = idx - r * kw;
            xsh[i * 68 + r] = in[(rowbase + r) * IN + kc + i];
        }
        __syncthreads();
        for (int i = 0; i < kw; i++) {
            const unsigned long long w2 = packdup(Wsh[i * 193 + tid]);
            const ulonglong2* x2 = (const ulonglong2*)&xsh[i * 68];
#pragma unroll
            for (int rv = 0; rv < 16; rv++) {
                ulonglong2 xv = x2[rv];
                FFMA2(acc2[2 * rv + 0], w2, xv.x);
                FFMA2(acc2[2 * rv + 1], w2, xv.y);
            }
        }
        __syncthreads();
    }
    const float bv = bias[tid];
#pragma unroll 8
    for (int rv = 0; rv < 32; rv++) {
        float2 p = unpack2(acc2[rv]);
        gx[(rowbase + 2 * rv + 0) * GN + tid] = p.x + bv;
        gx[(rowbase + 2 * rv + 1) * GN + tid] = p.y + bv;
    }
}

// ---------------------------------------------------------------------------
// Recurrent scan, 384 threads / 12 warps, MBS=8 batches per block.
//   warp pair layout: half = warpid & 1 (j-range split), g = (warpid>>1)*32+lane.
//   Thread (g, half) accumulates gate g's dot product over j in
//   [32*half, 32*half+32) for ALL 8 batches (4 packed f32x2 accumulators).
//   The two j-halves write SEPARATE partial buffers ghs[half]; the pointwise
//   phase adds them -> no extra barrier (2 barriers/step total).
//   Weight regs: 32 packed = 64 regs/thread (spill-proof at 384 thr/SM).
//   h ping-pong in smem as float4[j][2] (batches 0-3, 4-7): warp-uniform
//   broadcast LDS.128. gx prefetched one step ahead; thread (g,half) handles
//   gx for batches 4*half..4*half+3.
// ---------------------------------------------------------------------------
__global__ __launch_bounds__(384, 1) void scan_kernel(
    int layer,
    const float* __restrict__ Whh_f, const float* __restrict__ bhh_f,
    const float* __restrict__ Whh_b, const float* __restrict__ bhh_b)
{
    const int dir  = blockIdx.x & 1;
    const int blk  = blockIdx.x >> 1;
    const int tid  = threadIdx.x;
    const int warpid = tid >> 5;
    const int lane = tid & 31;
    const int half = warpid & 1;                   // j-half
    const int g    = (warpid >> 1) * 32 + lane;    // gate 0..191
    const float* __restrict__ Whh = dir ? Whh_b : Whh_f;
    const float* __restrict__ bhh = dir ? bhh_b : bhh_f;
    const float* __restrict__ gx  = g_gx[dir];
    const int bbase  = blk * MBS;
    const int dirOff = dir ? HN : 0;

    __shared__ __align__(16) float4 h4[2][HN][2];    // [ping][j][batch-half]
    __shared__ __align__(16) float4 ghs[2][GN][2];   // [j-half][gate][batch-half]
    __shared__ __align__(16) float4 sxs[GN][2];      // [gate][batch-half]

    // weights for this thread's j-range -> 32 packed-dup registers
    unsigned long long w2[32];
    {
        const float* wrow = Whh + (long)g * HN + 32 * half;
#pragma unroll
        for (int q = 0; q < 32; q++) w2[q] = packdup(wrow[q]);
    }
    // bias folded into half-0's partial only
    const unsigned long long bh2 = half ? 0ull : packdup(bhh[g]);

    // zero both h pings
    for (int idx = tid; idx < 2 * HN * 2; idx += 384)
        ((float4*)h4)[idx] = make_float4(0.f, 0.f, 0.f, 0.f);
    __syncthreads();

    // walking gx pointer: batches 4*half .. 4*half+3, gate g
    const long stepoff = dir ? -(long)GN : (long)GN;
    const long t0 = dir ? (TN - 1) : 0;
    const long BSTR = (long)TN * GN;               // batch stride in g_gx
    const float* gp = gx + ((long)(bbase + 4 * half) * TN + t0) * GN + g;

    // preload step 0
    float xg[4];
#pragma unroll
    for (int k = 0; k < 4; k++) xg[k] = __ldg(gp + k * BSTR);
    gp += stepoff;

    float* __restrict__ seq = (layer == 0) ? g_out0 : nullptr;
    int p = 0;

    for (int s = 0; s < TN; ++s) {
        const int t = dir ? (TN - 1 - s) : s;

        // prefetch step s+1 (over/under-run <= 1 row, stays inside g_gx)
        float xgn[4];
#pragma unroll
        for (int k = 0; k < 4; k++) xgn[k] = __ldg(gp + k * BSTR);
        gp += stepoff;

        // partial dot products over this thread's j-half, all 8 batches
        unsigned long long a01 = bh2, a23 = bh2, a45 = bh2, a67 = bh2;
        const ulonglong2* hp = (const ulonglong2*)h4[p];
#pragma unroll
        for (int q = 0; q < 32; q++) {
            const int j = 32 * half + q;
            const ulonglong2 h0 = hp[2 * j + 0];    // batches 0-3 (broadcast)
            const ulonglong2 h1 = hp[2 * j + 1];    // batches 4-7
            FFMA2(a01, w2[q], h0.x);
            FFMA2(a23, w2[q], h0.y);
            FFMA2(a45, w2[q], h1.x);
            FFMA2(a67, w2[q], h1.y);
        }
        {
            float2 u0 = unpack2(a01), u1 = unpack2(a23);
            float2 u2 = unpack2(a45), u3 = unpack2(a67);
            ghs[half][g][0] = make_float4(u0.x, u0.y, u1.x, u1.y);
            ghs[half][g][1] = make_float4(u2.x, u2.y, u3.x, u3.y);
            sxs[g][half] = make_float4(xg[0], xg[1], xg[2], xg[3]);
        }
#pragma unroll
        for (int k = 0; k < 4; k++) xg[k] = xgn[k];
        __syncthreads();

        // pointwise: 512 items over 384 threads; item -> (hu, b)
        {
            const float* gA  = (const float*)ghs;          // half 0 partials
            const float* gB  = gA + GN * 8;                // half 1 partials
            const float* sxf = (const float*)sxs;          // [gate*8 + b]
            const float* hOld = (const float*)h4[p];
            float* hNew = (float*)h4[p ^ 1];
            for (int item = tid; item < MBS * HN; item += 384) {
                const int b = item & 7, hu = item >> 3;
                const int ir = hu * 8 + b;
                const int iz = (64 + hu) * 8 + b;
                const int in_ = (128 + hu) * 8 + b;
                const float r = sigf(sxf[ir] + gA[ir] + gB[ir]);
                const float z = sigf(sxf[iz] + gA[iz] + gB[iz]);
                const float n = tanhfast(sxf[in_] + r * (gA[in_] + gB[in_]));
                const float hold = hOld[hu * 8 + b];
                const float hnew = n + z * (hold - n);
                hNew[hu * 8 + b] = hnew;
                if (seq)
                    seq[((long)(bbase + b) * TN + t) * (2 * HN) + dirOff + hu] = hnew;
            }
        }
        p ^= 1;
        __syncthreads();
    }

    if (layer == 1) {
        const float* hf = (const float*)h4[p];
        for (int item = tid; item < MBS * HN; item += 384) {
            const int b = item & 7, hu = item >> 3;
            g_emb[(bbase + b) * (2 * HN) + dirOff + hu] = hf[hu * 8 + b];
        }
    }
}

// ---------------------------------------------------------------------------
// Head: LayerNorm(128) -> ReLU(W1) -> W2. One block per batch row.
// ---------------------------------------------------------------------------
__global__ __launch_bounds__(128) void head_kernel(
    const float* __restrict__ ln_g, const float* __restrict__ ln_b,
    const float* __restrict__ W1, const float* __restrict__ b1,
    const float* __restrict__ W2, const float* __restrict__ b2,
    float* __restrict__ out)
{
    const int b = blockIdx.x, tid = threadIdx.x;
    __shared__ float ysh[128], hsh[64], red[8];

    const float e = g_emb[b * 128 + tid];
    float s = e, q = e * e;
#pragma unroll
    for (int o = 16; o > 0; o >>= 1) {
        s += __shfl_down_sync(~0u, s, o);
        q += __shfl_down_sync(~0u, q, o);
    }
    if ((tid & 31) == 0) { red[tid >> 5] = s; red[4 + (tid >> 5)] = q; }
    __syncthreads();
    const float ssum = red[0] + red[1] + red[2] + red[3];
    const float qsum = red[4] + red[5] + red[6] + red[7];
    const float mu = ssum * (1.f / 128.f);
    const float var = qsum * (1.f / 128.f) - mu * mu;
    ysh[tid] = (e - mu) * rsqrtf(var + 1e-5f) * ln_g[tid] + ln_b[tid];
    __syncthreads();
    if (tid < 64) {
        float a = b1[tid];
#pragma unroll 8
        for (int i = 0; i < 128; i++) a += ysh[i] * W1[tid * 128 + i];
        hsh[tid] = fmaxf(a, 0.f);
    }
    __syncthreads();
    if (tid < 11) {
        float a = b2[tid];
#pragma unroll
        for (int i = 0; i < 64; i++) a += hsh[i] * W2[tid * 64 + i];
        out[b * 11 + tid] = a;
    }
}

// ---------------------------------------------------------------------------
extern "C" void kernel_launch(void* const* d_in, const int* in_sizes, int n_in,
                              void* d_out, int out_size)
{
    const float* x     = (const float*)d_in[0];
    const float* Wih00 = (const float*)d_in[1];
    const float* Whh00 = (const float*)d_in[2];
    const float* bih00 = (const float*)d_in[3];
    const float* bhh00 = (const float*)d_in[4];
    const float* Wih01 = (const float*)d_in[5];
    const float* Whh01 = (const float*)d_in[6];
    const float* bih01 = (const float*)d_in[7];
    const float* bhh01 = (const float*)d_in[8];
    const float* Wih10 = (const float*)d_in[9];
    const float* Whh10 = (const float*)d_in[10];
    const float* bih10 = (const float*)d_in[11];
    const float* bhh10 = (const float*)d_in[12];
    const float* Wih11 = (const float*)d_in[13];
    const float* Whh11 = (const float*)d_in[14];
    const float* bih11 = (const float*)d_in[15];
    const float* bhh11 = (const float*)d_in[16];
    const float* ln_g  = (const float*)d_in[17];
    const float* ln_b  = (const float*)d_in[18];
    const float* W1    = (const float*)d_in[19];
    const float* b1    = (const float*)d_in[20];
    const float* W2    = (const float*)d_in[21];
    const float* b2    = (const float*)d_in[22];
    float* out = (float*)d_out;

    const dim3 gxGrid(BN * TN / 64, 2);
    const int scBlocks = (BN / MBS) * 2;   // dir folded into blockIdx.x -> 64

    // Layer 0: input gates from x (IN=29), then bidirectional scan -> g_out0
    gx_kernel<29><<<gxGrid, 192>>>(x, 0, Wih00, bih00, Wih01, bih01);
    scan_kernel<<<scBlocks, 384>>>(0, Whh00, bhh00, Whh01, bhh01);

    // Layer 1: input gates from g_out0 (IN=128), then scan -> g_emb
    gx_kernel<128><<<gxGrid, 192>>>(x, 1, Wih10, bih10, Wih11, bih11);
    scan_kernel<<<scBlocks, 384>>>(1, Whh10, bhh10, Whh11, bhh11);

    // Head
    head_kernel<<<BN, 128>>>(ln_g, ln_b, W1, b1, W2, b2, out);
}

// round 14
// speedup vs baseline: 1.3221x; 1.3221x over previous
#include <cuda_runtime.h>
#include <cuda_bf16.h>

#define BN 256
#define TN 2048
#define HN 64
#define GN 192   /* 3*H */
#define MB 4     /* batches per scan block */

// ---------------------------------------------------------------------------
// Scratch (no allocation allowed -> __device__ globals)
// NOTE: scan prefetch (distance 2) deliberately over/under-runs up to two rows
// past its direction slab; layout [2][...] keeps those accesses inside this
// object for both directions at both edges.
// ---------------------------------------------------------------------------
__device__ float g_gx[2][(size_t)BN * TN * GN];        // per-direction input gates
__device__ float g_out0[(size_t)BN * TN * 2 * HN];     // layer-0 output [B*T, 128]
__device__ float g_emb[BN * 2 * HN];                   // layer-1 final states [B, 128]

__device__ __forceinline__ float sigf(float x) {
    return __fdividef(1.f, 1.f + __expf(-x));
}
__device__ __forceinline__ float tanhfast(float x) {
    x = fminf(fmaxf(x, -15.f), 15.f);
    float e = __expf(-2.f * x);
    return __fdividef(1.f - e, 1.f + e);
}

// Packed fp32x2 helpers (Blackwell dual-rate fp32 path)
#define FFMA2(acc, a, b) \
    asm("fma.rn.f32x2 %0, %1, %2, %0;" : "+l"(acc) : "l"(a), "l"(b))

__device__ __forceinline__ unsigned long long packdup(float v) {
    unsigned long long r;
    asm("mov.b64 %0, {%1, %1};" : "=l"(r) : "f"(v));
    return r;
}
__device__ __forceinline__ float2 unpack2(unsigned long long p) {
    float2 f;
    asm("mov.b64 {%0, %1}, %2;" : "=f"(f.x), "=f"(f.y) : "l"(p));
    return f;
}

// ---------------------------------------------------------------------------
// Input-gate GEMM: gx[row, g] = bih[g] + sum_i in[row, i] * Wih[g, i]
// 64 rows/block, 192 threads (one gate each), K chunked by 32 via smem.
// ---------------------------------------------------------------------------
template <int IN>
__global__ __launch_bounds__(192) void gx_kernel(
    const float* __restrict__ xin, int use_out0,
    const float* __restrict__ Wf, const float* __restrict__ bf,
    const float* __restrict__ Wb, const float* __restrict__ bb)
{
    const int dir = blockIdx.y;
    const float* __restrict__ W    = dir ? Wb : Wf;
    const float* __restrict__ bias = dir ? bb : bf;
    const float* __restrict__ in   = use_out0 ? g_out0 : xin;
    float* __restrict__ gx = g_gx[dir];
    const int tid = threadIdx.x;
    const long rowbase = (long)blockIdx.x * 64;

    __shared__ float Wsh[32 * 193];   // [i][g]
    __shared__ float xsh[32 * 68];    // [i][r], 16B-aligned rows

    unsigned long long acc2[32];      // 32 packed pairs = 64 row accumulators
#pragma unroll
    for (int rv = 0; rv < 32; rv++) acc2[rv] = 0ull;

#pragma unroll
    for (int kc = 0; kc < IN; kc += 32) {
        const int kw = (IN - kc < 32) ? (IN - kc) : 32;
        for (int idx = tid; idx < kw * 192; idx += 192) {
            int g = idx / kw, i = idx - g * kw;
            Wsh[i * 193 + g] = W[(long)g * IN + kc + i];
        }
        for (int idx = tid; idx < kw * 64; idx += 192) {
            int r = idx / kw, i = idx - r * kw;
            xsh[i * 68 + r] = in[(rowbase + r) * IN + kc + i];
        }
        __syncthreads();
        for (int i = 0; i < kw; i++) {
            const unsigned long long w2 = packdup(Wsh[i * 193 + tid]);
            const ulonglong2* x2 = (const ulonglong2*)&xsh[i * 68];
#pragma unroll
            for (int rv = 0; rv < 16; rv++) {
                ulonglong2 xv = x2[rv];
                FFMA2(acc2[2 * rv + 0], w2, xv.x);
                FFMA2(acc2[2 * rv + 1], w2, xv.y);
            }
        }
        __syncthreads();
    }
    const float bv = bias[tid];
#pragma unroll 8
    for (int rv = 0; rv < 32; rv++) {
        float2 p = unpack2(acc2[rv]);
        gx[(rowbase + 2 * rv + 0) * GN + tid] = p.x + bv;
        gx[(rowbase + 2 * rv + 1) * GN + tid] = p.y + bv;
    }
}

// ---------------------------------------------------------------------------
// Recurrent scan: MB=4 batches/block (128 blocks, 1/SM), 384 threads/12 warps.
//   half = warpid & 1 splits the j-dimension: thread (g, half) accumulates
//   gate g's partial dot over j in [32*half, 32*half+32) for all 4 batches.
//   FOUR accumulator chains (2 j-sub-chains x 2 batch-pairs): RAW depth 16.
//   Halves write separate partial buffers ghs[half]; pointwise sums them.
//   Weights: 32 packed-dup = 64 regs/thread (spill-proof at 384 thr).
//   h ping-pong in smem as float4[j] (batches 0-3): warp-uniform LDS.128.
//   gx prefetched TWO steps ahead; thread (g,half) loads batches 2half,2half+1.
// ---------------------------------------------------------------------------
__global__ __launch_bounds__(384, 1) void scan_kernel(
    int layer,
    const float* __restrict__ Whh_f, const float* __restrict__ bhh_f,
    const float* __restrict__ Whh_b, const float* __restrict__ bhh_b)
{
    const int dir  = blockIdx.x & 1;
    const int blk  = blockIdx.x >> 1;
    const int tid  = threadIdx.x;
    const int warpid = tid >> 5;
    const int lane = tid & 31;
    const int half = warpid & 1;                   // j-half
    const int g    = (warpid >> 1) * 32 + lane;    // gate 0..191
    const float* __restrict__ Whh = dir ? Whh_b : Whh_f;
    const float* __restrict__ bhh = dir ? bhh_b : bhh_f;
    const float* __restrict__ gx  = g_gx[dir];
    const int bbase  = blk * MB;
    const int dirOff = dir ? HN : 0;

    __shared__ __align__(16) float4 h4[2][HN];     // [ping][j] = batches 0..3
    __shared__ __align__(16) float4 ghs[2][GN];    // [j-half][gate] partials
    __shared__ __align__(16) float2 sx2[GN][2];    // [gate][batch-pair]

    // weights for this thread's j-half -> 32 packed-dup registers (64 regs)
    unsigned long long w2[32];
    {
        const float* wrow = Whh + (long)g * HN + 32 * half;
#pragma unroll
        for (int q = 0; q < 32; q++) w2[q] = packdup(wrow[q]);
    }
    // bias folded into half-0's A-chain only
    const unsigned long long bh2 = half ? 0ull : packdup(bhh[g]);

    // zero both h pings
    for (int idx = tid; idx < 2 * HN; idx += 384)
        ((float4*)h4)[idx] = make_float4(0.f, 0.f, 0.f, 0.f);
    __syncthreads();

    // walking gx pointers: this thread covers batches 2*half, 2*half+1
    const long stepoff = dir ? -(long)GN : (long)GN;
    const long t0 = dir ? (TN - 1) : 0;
    const long BSTR = (long)TN * GN;
    const float* gp = gx + ((long)(bbase + 2 * half) * TN + t0) * GN + g;

    // preload steps 0 and 1 (distance-2 pipeline)
    float xa0 = __ldg(gp), xb0 = __ldg(gp + BSTR); gp += stepoff;
    float xa1 = __ldg(gp), xb1 = __ldg(gp + BSTR); gp += stepoff;

    float* __restrict__ seq = (layer == 0) ? g_out0 : nullptr;
    int p = 0;

    for (int s = 0; s < TN; ++s) {
        const int t = dir ? (TN - 1 - s) : s;

        // prefetch step s+2 (over/under-run <= 2 rows, stays inside g_gx)
        const float xa2 = __ldg(gp), xb2 = __ldg(gp + BSTR); gp += stepoff;

        // partial dot products: 4 chains, RAW depth 16 each
        unsigned long long a01A = bh2, a23A = bh2;
        unsigned long long a01B = 0ull, a23B = 0ull;
        const ulonglong2* hp = (const ulonglong2*)h4[p] + 32 * half;
#pragma unroll
        for (int q = 0; q < 16; q++) {
            const ulonglong2 h0 = hp[q];          // broadcast LDS.128
            const ulonglong2 h1 = hp[16 + q];
            FFMA2(a01A, w2[q],      h0.x);
            FFMA2(a23A, w2[q],      h0.y);
            FFMA2(a01B, w2[16 + q], h1.x);
            FFMA2(a23B, w2[16 + q], h1.y);
        }
        {
            float2 uA0 = unpack2(a01A), uB0 = unpack2(a01B);
            float2 uA1 = unpack2(a23A), uB1 = unpack2(a23B);
            ghs[half][g] = make_float4(uA0.x + uB0.x, uA0.y + uB0.y,
                                       uA1.x + uB1.x, uA1.y + uB1.y);
            sx2[g][half] = make_float2(xa0, xb0);
        }
        xa0 = xa1; xb0 = xb1;
        xa1 = xa2; xb1 = xb2;
        __syncthreads();

        // pointwise: 256 items on threads 0..255; item -> (hu, b)
        if (tid < MB * HN) {
            const int b = tid & 3, hu = tid >> 2;
            const float* gA  = (const float*)ghs[0];   // gate*4 + b
            const float* gB  = (const float*)ghs[1];
            const float* sxf = (const float*)sx2;      // gate*4 + b (2x float2)
            const int ir  = hu * 4 + b;
            const int iz  = (64 + hu) * 4 + b;
            const int in_ = (128 + hu) * 4 + b;
            const float r = sigf(sxf[ir] + gA[ir] + gB[ir]);
            const float z = sigf(sxf[iz] + gA[iz] + gB[iz]);
            const float n = tanhfast(sxf[in_] + r * (gA[in_] + gB[in_]));
            const float hold = ((const float*)h4[p])[ir];
            const float hnew = n + z * (hold - n);
            ((float*)h4[p ^ 1])[ir] = hnew;
            if (seq)
                seq[((long)(bbase + b) * TN + t) * (2 * HN) + dirOff + hu] = hnew;
        }
        p ^= 1;
        __syncthreads();
    }

    if (layer == 1 && tid < MB * HN) {
        const int b = tid & 3, hu = tid >> 2;
        g_emb[(bbase + b) * (2 * HN) + dirOff + hu] = ((const float*)h4[p])[hu * 4 + b];
    }
}

// ---------------------------------------------------------------------------
// Head: LayerNorm(128) -> ReLU(W1) -> W2. One block per batch row.
// ---------------------------------------------------------------------------
__global__ __launch_bounds__(128) void head_kernel(
    const float* __restrict__ ln_g, const float* __restrict__ ln_b,
    const float* __restrict__ W1, const float* __restrict__ b1,
    const float* __restrict__ W2, const float* __restrict__ b2,
    float* __restrict__ out)
{
    const int b = blockIdx.x, tid = threadIdx.x;
    __shared__ float ysh[128], hsh[64], red[8];

    const float e = g_emb[b * 128 + tid];
    float s = e, q = e * e;
#pragma unroll
    for (int o = 16; o > 0; o >>= 1) {
        s += __shfl_down_sync(~0u, s, o);
        q += __shfl_down_sync(~0u, q, o);
    }
    if ((tid & 31) == 0) { red[tid >> 5] = s; red[4 + (tid >> 5)] = q; }
    __syncthreads();
    const float ssum = red[0] + red[1] + red[2] + red[3];
    const float qsum = red[4] + red[5] + red[6] + red[7];
    const float mu = ssum * (1.f / 128.f);
    const float var = qsum * (1.f / 128.f) - mu * mu;
    ysh[tid] = (e - mu) * rsqrtf(var + 1e-5f) * ln_g[tid] + ln_b[tid];
    __syncthreads();
    if (tid < 64) {
        float a = b1[tid];
#pragma unroll 8
        for (int i = 0; i < 128; i++) a += ysh[i] * W1[tid * 128 + i];
        hsh[tid] = fmaxf(a, 0.f);
    }
    __syncthreads();
    if (tid < 11) {
        float a = b2[tid];
#pragma unroll
        for (int i = 0; i < 64; i++) a += hsh[i] * W2[tid * 64 + i];
        out[b * 11 + tid] = a;
    }
}

// ---------------------------------------------------------------------------
extern "C" void kernel_launch(void* const* d_in, const int* in_sizes, int n_in,
                              void* d_out, int out_size)
{
    const float* x     = (const float*)d_in[0];
    const float* Wih00 = (const float*)d_in[1];
    const float* Whh00 = (const float*)d_in[2];
    const float* bih00 = (const float*)d_in[3];
    const float* bhh00 = (const float*)d_in[4];
    const float* Wih01 = (const float*)d_in[5];
    const float* Whh01 = (const float*)d_in[6];
    const float* bih01 = (const float*)d_in[7];
    const float* bhh01 = (const float*)d_in[8];
    const float* Wih10 = (const float*)d_in[9];
    const float* Whh10 = (const float*)d_in[10];
    const float* bih10 = (const float*)d_in[11];
    const float* bhh10 = (const float*)d_in[12];
    const float* Wih11 = (const float*)d_in[13];
    const float* Whh11 = (const float*)d_in[14];
    const float* bih11 = (const float*)d_in[15];
    const float* bhh11 = (const float*)d_in[16];
    const float* ln_g  = (const float*)d_in[17];
    const float* ln_b  = (const float*)d_in[18];
    const float* W1    = (const float*)d_in[19];
    const float* b1    = (const float*)d_in[20];
    const float* W2    = (const float*)d_in[21];
    const float* b2    = (const float*)d_in[22];
    float* out = (float*)d_out;

    const dim3 gxGrid(BN * TN / 64, 2);
    const int scBlocks = (BN / MB) * 2;   // dir folded into blockIdx.x -> 128

    // Layer 0: input gates from x (IN=29), then bidirectional scan -> g_out0
    gx_kernel<29><<<gxGrid, 192>>>(x, 0, Wih00, bih00, Wih01, bih01);
    scan_kernel<<<scBlocks, 384>>>(0, Whh00, bhh00, Whh01, bhh01);

    // Layer 1: input gates from g_out0 (IN=128), then scan -> g_emb
    gx_kernel<128><<<gxGrid, 192>>>(x, 1, Wih10, bih10, Wih11, bih11);
    scan_kernel<<<scBlocks, 384>>>(1, Whh10, bhh10, Whh11, bhh11);

    // Head
    head_kernel<<<BN, 128>>>(ln_g, ln_b, W1, b1, W2, b2, out);
}

// round 15
// speedup vs baseline: 2.1671x; 1.6391x over previous
#include <cuda_runtime.h>
#include <cuda_bf16.h>

#define BN 256
#define TN 2048
#define HN 64
#define GN 192   /* 3*H */
#define MB 4     /* batches per scan block */

// ---------------------------------------------------------------------------
// Scratch (no allocation allowed -> __device__ globals)
// NOTE: scan prefetch (distance 3) deliberately over/under-runs up to three
// rows past its direction slab; layout [2][...] keeps those accesses inside
// this object for both directions at both edges.
// ---------------------------------------------------------------------------
__device__ float g_gx[2][(size_t)BN * TN * GN];        // per-direction input gates
__device__ float g_out0[(size_t)BN * TN * 2 * HN];     // layer-0 output [B*T, 128]
__device__ float g_emb[BN * 2 * HN];                   // layer-1 final states [B, 128]

__device__ __forceinline__ float sigf(float x) {
    return __fdividef(1.f, 1.f + __expf(-x));
}
__device__ __forceinline__ float tanhfast(float x) {
    x = fminf(fmaxf(x, -15.f), 15.f);
    float e = __expf(-2.f * x);
    return __fdividef(1.f - e, 1.f + e);
}

// Packed fp32x2 helpers (Blackwell dual-rate fp32 path)
#define FFMA2(acc, a, b) \
    asm("fma.rn.f32x2 %0, %1, %2, %0;" : "+l"(acc) : "l"(a), "l"(b))

__device__ __forceinline__ unsigned long long packdup(float v) {
    unsigned long long r;
    asm("mov.b64 %0, {%1, %1};" : "=l"(r) : "f"(v));
    return r;
}
__device__ __forceinline__ float2 unpack2(unsigned long long p) {
    float2 f;
    asm("mov.b64 {%0, %1}, %2;" : "=f"(f.x), "=f"(f.y) : "l"(p));
    return f;
}

// ---------------------------------------------------------------------------
// Input-gate GEMM v2: gx[row, g] = bih[g] + sum_i in[row, i] * Wih[g, i]
// 64 rows x 192 gates per block, 192 threads. Thread owns 4 consecutive
// gates x 16 rows. W staged PRE-DUPLICATED (ull pairs) so the inner step is
// 2 LDS.128 (4 dup gate weights) + 4 LDS.128 (16 rows) + 32 FFMA2.
// ---------------------------------------------------------------------------
template <int IN>
__global__ __launch_bounds__(192) void gx_kernel(
    const float* __restrict__ xin, int use_out0,
    const float* __restrict__ Wf, const float* __restrict__ bf,
    const float* __restrict__ Wb, const float* __restrict__ bb)
{
    const int dir = blockIdx.y;
    const float* __restrict__ W    = dir ? Wb : Wf;
    const float* __restrict__ bias = dir ? bb : bf;
    const float* __restrict__ in   = use_out0 ? g_out0 : xin;
    float* __restrict__ gx = g_gx[dir];
    const int tid = threadIdx.x;
    const long rowbase = (long)blockIdx.x * 64;

    const int gq    = (tid % 48) * 4;     // first of 4 consecutive gates
    const int rbase = (tid / 48) * 16;    // first of 16 rows

    __shared__ unsigned long long Wdup[32 * 194];  // [i][g] dup pairs, padded
    __shared__ float xsh[32 * 68];                 // [i][r], 16B-aligned rows

    unsigned long long acc[32];   // [gate 0..3][rowpair 0..7]
#pragma unroll
    for (int q = 0; q < 32; q++) acc[q] = 0ull;

#pragma unroll
    for (int kc = 0; kc < IN; kc += 32) {
        const int kw = (IN - kc < 32) ? (IN - kc) : 32;
        // stage W duplicated (coalesced over i within each gate row)
        for (int idx = tid; idx < kw * 192; idx += 192) {
            int g = idx / kw, i = idx - g * kw;
            Wdup[i * 194 + g] = packdup(W[(long)g * IN + kc + i]);
        }
        // stage x chunk transposed
        for (int idx = tid; idx < kw * 64; idx += 192) {
            int r = idx / kw, i = idx - r * kw;
            xsh[i * 68 + r] = in[(rowbase + r) * IN + kc + i];
        }
        __syncthreads();
        for (int i = 0; i < kw; i++) {
            const ulonglong2* wp = (const ulonglong2*)&Wdup[i * 194 + gq];
            const ulonglong2 wA = wp[0];   // gates gq, gq+1 (dupped)
            const ulonglong2 wB = wp[1];   // gates gq+2, gq+3
            const ulonglong2* x2 = (const ulonglong2*)&xsh[i * 68 + rbase];
            ulonglong2 xv[4];
#pragma unroll
            for (int k = 0; k < 4; k++) xv[k] = x2[k];   // 16 rows = 8 pairs
            const unsigned long long* xr = (const unsigned long long*)xv;
#pragma unroll
            for (int rp = 0; rp < 8; rp++) {
                FFMA2(acc[0 * 8 + rp], wA.x, xr[rp]);
                FFMA2(acc[1 * 8 + rp], wA.y, xr[rp]);
                FFMA2(acc[2 * 8 + rp], wB.x, xr[rp]);
                FFMA2(acc[3 * 8 + rp], wB.y, xr[rp]);
            }
        }
        __syncthreads();
    }
    // epilogue: 16 rows x STG.128 of 4 gates
    const float4 bv = *(const float4*)&bias[gq];
#pragma unroll
    for (int r = 0; r < 16; r++) {
        const int rp = r >> 1, hi = r & 1;
        float2 p0 = unpack2(acc[0 * 8 + rp]);
        float2 p1 = unpack2(acc[1 * 8 + rp]);
        float2 p2 = unpack2(acc[2 * 8 + rp]);
        float2 p3 = unpack2(acc[3 * 8 + rp]);
        float4 o;
        o.x = (hi ? p0.y : p0.x) + bv.x;
        o.y = (hi ? p1.y : p1.x) + bv.y;
        o.z = (hi ? p2.y : p2.x) + bv.z;
        o.w = (hi ? p3.y : p3.x) + bv.w;
        *(float4*)&gx[(rowbase + rbase + r) * GN + gq] = o;
    }
}

// ---------------------------------------------------------------------------
// Recurrent scan: MB=4 batches/block (128 blocks), 384 threads / 12 warps.
//   Thread layout: jq = warpid & 3 (j-quarter of 16), gbase = (warpid>>2)*32
//   + lane; thread owns gates g0=gbase and g1=gbase+96 over its 16 j.
//   Per step: 16 LDS.128 (h, warp-uniform broadcast) feed 64 FFMA2
//   (2 gates x 2 batch-pairs per load) -- HALF the LDS of the previous
//   layout. 4 partial buffers ghs[jq] written as raw packed STS.128 (no
//   unpack); pointwise sums the 4 partials. Weights: 32 packed-dup = 64 regs.
//   gx prefetched THREE steps ahead; thread (g0,g1,jq) loads batch jq.
// ---------------------------------------------------------------------------
__global__ __launch_bounds__(384, 1) void scan_kernel(
    int layer,
    const float* __restrict__ Whh_f, const float* __restrict__ bhh_f,
    const float* __restrict__ Whh_b, const float* __restrict__ bhh_b)
{
    const int dir  = blockIdx.x & 1;
    const int blk  = blockIdx.x >> 1;
    const int tid  = threadIdx.x;
    const int warpid = tid >> 5;
    const int lane = tid & 31;
    const int jq   = warpid & 3;                   // j-quarter (also batch id)
    const int g0   = (warpid >> 2) * 32 + lane;    // gate 0..95
    const int g1   = g0 + 96;                      // gate 96..191
    const float* __restrict__ Whh = dir ? Whh_b : Whh_f;
    const float* __restrict__ bhh = dir ? bhh_b : bhh_f;
    const float* __restrict__ gx  = g_gx[dir];
    const int bbase  = blk * MB;
    const int dirOff = dir ? HN : 0;

    __shared__ __align__(16) float4 h4[2][HN];       // [ping][j] = batches 0..3
    __shared__ __align__(16) ulonglong2 ghs[4][GN];  // [jq][gate] packed partials
    __shared__ float sxs[GN * 5];                    // [gate*5 + b] (5: bank-spread)

    // weights for (g0, g1) over this j-quarter -> 32 packed-dup regs
    unsigned long long wa[16], wb[16];
    {
        const float* r0 = Whh + (long)g0 * HN + 16 * jq;
        const float* r1 = Whh + (long)g1 * HN + 16 * jq;
#pragma unroll
        for (int q = 0; q < 16; q++) { wa[q] = packdup(r0[q]); wb[q] = packdup(r1[q]); }
    }
    // bias folded into quarter 0 only
    const unsigned long long bh2a = (jq == 0) ? packdup(bhh[g0]) : 0ull;
    const unsigned long long bh2b = (jq == 0) ? packdup(bhh[g1]) : 0ull;

    for (int idx = tid; idx < 2 * HN; idx += 384)
        ((float4*)h4)[idx] = make_float4(0.f, 0.f, 0.f, 0.f);
    __syncthreads();

    // walking gx pointer: batch jq, gates g0 / g0+96
    const long stepoff = dir ? -(long)GN : (long)GN;
    const long t0 = dir ? (TN - 1) : 0;
    const float* gp = gx + ((long)(bbase + jq) * TN + t0) * GN + g0;

    // preload steps 0..2 (distance-3 pipeline)
    float xa0 = __ldg(gp), xb0 = __ldg(gp + 96); gp += stepoff;
    float xa1 = __ldg(gp), xb1 = __ldg(gp + 96); gp += stepoff;
    float xa2 = __ldg(gp), xb2 = __ldg(gp + 96); gp += stepoff;

    float* __restrict__ seq = (layer == 0) ? g_out0 : nullptr;
    int p = 0;

    for (int s = 0; s < TN; ++s) {
        const int t = dir ? (TN - 1 - s) : s;

        // prefetch step s+3 (over/under-run <= 3 rows, stays inside g_gx)
        const float xa3 = __ldg(gp), xb3 = __ldg(gp + 96); gp += stepoff;

        // partial dots: 2 gates x 2 batch-pair chains, 16 LDS feed 64 FFMA2
        unsigned long long aA01 = bh2a, aA23 = bh2a;
        unsigned long long aB01 = bh2b, aB23 = bh2b;
        const ulonglong2* hp = (const ulonglong2*)h4[p] + 16 * jq;
#pragma unroll
        for (int q = 0; q < 16; q++) {
            const ulonglong2 hq = hp[q];      // broadcast LDS.128 (4 batches)
            FFMA2(aA01, wa[q], hq.x);
            FFMA2(aA23, wa[q], hq.y);
            FFMA2(aB01, wb[q], hq.x);
            FFMA2(aB23, wb[q], hq.y);
        }
        {
            ulonglong2 sA; sA.x = aA01; sA.y = aA23;
            ulonglong2 sB; sB.x = aB01; sB.y = aB23;
            ghs[jq][g0] = sA;                 // raw packed STS.128
            ghs[jq][g1] = sB;
            sxs[g0 * 5 + jq] = xa0;
            sxs[g1 * 5 + jq] = xb0;
        }
        xa0 = xa1; xb0 = xb1;
        xa1 = xa2; xb1 = xb2;
        xa2 = xa3; xb2 = xb3;
        __syncthreads();

        // pointwise: 256 items on threads 0..255; sums 4 partials
        if (tid < MB * HN) {
            const int b = tid & 3, hu = tid >> 2;
            const float* G = (const float*)ghs;          // [q][gate][b]
            const int ir  = hu * 4 + b;
            const int iz  = (64 + hu) * 4 + b;
            const int in_ = (128 + hu) * 4 + b;
            const float ghr = G[ir]  + G[GN*4 + ir]  + G[GN*8 + ir]  + G[GN*12 + ir];
            const float ghz = G[iz]  + G[GN*4 + iz]  + G[GN*8 + iz]  + G[GN*12 + iz];
            const float ghn = G[in_] + G[GN*4 + in_] + G[GN*8 + in_] + G[GN*12 + in_];
            const float r = sigf(sxs[hu * 5 + b] + ghr);
            const float z = sigf(sxs[(64 + hu) * 5 + b] + ghz);
            const float n = tanhfast(sxs[(128 + hu) * 5 + b] + r * ghn);
            const float hold = ((const float*)h4[p])[ir];
            const float hnew = n + z * (hold - n);
            ((float*)h4[p ^ 1])[ir] = hnew;
            if (seq)
                seq[((long)(bbase + b) * TN + t) * (2 * HN) + dirOff + hu] = hnew;
        }
        p ^= 1;
        __syncthreads();
    }

    if (layer == 1 && tid < MB * HN) {
        const int b = tid & 3, hu = tid >> 2;
        g_emb[(bbase + b) * (2 * HN) + dirOff + hu] = ((const float*)h4[p])[hu * 4 + b];
    }
}

// ---------------------------------------------------------------------------
// Head: LayerNorm(128) -> ReLU(W1) -> W2. One block per batch row.
// ---------------------------------------------------------------------------
__global__ __launch_bounds__(128) void head_kernel(
    const float* __restrict__ ln_g, const float* __restrict__ ln_b,
    const float* __restrict__ W1, const float* __restrict__ b1,
    const float* __restrict__ W2, const float* __restrict__ b2,
    float* __restrict__ out)
{
    const int b = blockIdx.x, tid = threadIdx.x;
    __shared__ float ysh[128], hsh[64], red[8];

    const float e = g_emb[b * 128 + tid];
    float s = e, q = e * e;
#pragma unroll
    for (int o = 16; o > 0; o >>= 1) {
        s += __shfl_down_sync(~0u, s, o);
        q += __shfl_down_sync(~0u, q, o);
    }
    if ((tid & 31) == 0) { red[tid >> 5] = s; red[4 + (tid >> 5)] = q; }
    __syncthreads();
    const float ssum = red[0] + red[1] + red[2] + red[3];
    const float qsum = red[4] + red[5] + red[6] + red[7];
    const float mu = ssum * (1.f / 128.f);
    const float var = qsum * (1.f / 128.f) - mu * mu;
    ysh[tid] = (e - mu) * rsqrtf(var + 1e-5f) * ln_g[tid] + ln_b[tid];
    __syncthreads();
    if (tid < 64) {
        float a = b1[tid];
#pragma unroll 8
        for (int i = 0; i < 128; i++) a += ysh[i] * W1[tid * 128 + i];
        hsh[tid] = fmaxf(a, 0.f);
    }
    __syncthreads();
    if (tid < 11) {
        float a = b2[tid];
#pragma unroll
        for (int i = 0; i < 64; i++) a += hsh[i] * W2[tid * 64 + i];
        out[b * 11 + tid] = a;
    }
}

// ---------------------------------------------------------------------------
extern "C" void kernel_launch(void* const* d_in, const int* in_sizes, int n_in,
                              void* d_out, int out_size)
{
    const float* x     = (const float*)d_in[0];
    const float* Wih00 = (const float*)d_in[1];
    const float* Whh00 = (const float*)d_in[2];
    const float* bih00 = (const float*)d_in[3];
    const float* bhh00 = (const float*)d_in[4];
    const float* Wih01 = (const float*)d_in[5];
    const float* Whh01 = (const float*)d_in[6];
    const float* bih01 = (const float*)d_in[7];
    const float* bhh01 = (const float*)d_in[8];
    const float* Wih10 = (const float*)d_in[9];
    const float* Whh10 = (const float*)d_in[10];
    const float* bih10 = (const float*)d_in[11];
    const float* bhh10 = (const float*)d_in[12];
    const float* Wih11 = (const float*)d_in[13];
    const float* Whh11 = (const float*)d_in[14];
    const float* bih11 = (const float*)d_in[15];
    const float* bhh11 = (const float*)d_in[16];
    const float* ln_g  = (const float*)d_in[17];
    const float* ln_b  = (const float*)d_in[18];
    const float* W1    = (const float*)d_in[19];
    const float* b1    = (const float*)d_in[20];
    const float* W2    = (const float*)d_in[21];
    const float* b2    = (const float*)d_in[22];
    float* out = (float*)d_out;

    const dim3 gxGrid(BN * TN / 64, 2);
    const int scBlocks = (BN / MB) * 2;   // dir folded into blockIdx.x -> 128

    // Layer 0: input gates from x (IN=29), then bidirectional scan -> g_out0
    gx_kernel<29><<<gxGrid, 192>>>(x, 0, Wih00, bih00, Wih01, bih01);
    scan_kernel<<<scBlocks, 384>>>(0, Whh00, bhh00, Whh01, bhh01);

    // Layer 1: input gates from g_out0 (IN=128), then scan -> g_emb
    gx_kernel<128><<<gxGrid, 192>>>(x, 1, Wih10, bih10, Wih11, bih11);
    scan_kernel<<<scBlocks, 384>>>(1, Whh10, bhh10, Whh11, bhh11);

    // Head
    head_kernel<<<BN, 128>>>(ln_g, ln_b, W1, b1, W2, b2, out);
}